// round 15
// baseline (speedup 1.0000x reference)
#include <cuda_runtime.h>
#include <math.h>

#define Nn 128
#define Cc 256
#define Aa 512
#define NB 128
#define NT1 512            // K1: 4 warps/SMSP for latency hiding
#define NT2 256
#define KSPLIT 8
#define TS 66              // smem row stride (floats): even (8B-aligned rows)

// Scratch (device globals — no allocations allowed).
__device__ float g_part[KSPLIT * 2 * Nn * Cc]; // K-split partials of [G;H]

// ===========================================================================
// K1: [G;H] = [s;t] @ W[:C]^T  — 16 output tiles (64x64) x 8-way K-split.
// 512 threads: per-thread 2 rows x 4 cols. Zeroes out[0] for K2's atomics.
// ===========================================================================
__global__ __launch_bounds__(NT1, 1)
void isda_gemm_kernel(const float* __restrict__ W,
                      const float* __restrict__ s,
                      const float* __restrict__ t,
                      float* __restrict__ out)
{
    __shared__ float Xs[64][TS];
    __shared__ float Ws[64][TS];
    const int tid = threadIdx.x;
    const int bid = blockIdx.x;

    const int mt = bid & 3;
    const int ct = (bid >> 2) & 3;
    const int kt = bid >> 4;
    const int m0 = mt * 64, c0 = ct * 64, kb = kt * 64;

    if (bid == 0 && tid == 0) out[0] = 0.0f;

    const float* xbase = (mt < 2) ? (s + (size_t)m0 * Aa)
                                  : (t + (size_t)(m0 - 128) * Aa);
    // Stage both 64x64 tiles: 1024 float4 per array, 512 threads x 2 iters.
#pragma unroll
    for (int i = 0; i < 2; ++i) {
        const int idx = tid + i * 512;            // 0..1023
        const int r = idx >> 4, kq = idx & 15;    // 16 float4 per 64-f row
        const float4 xv4 = *(const float4*)&xbase[(size_t)r * Aa + kb + kq * 4];
        const float4 wv4 = *(const float4*)&W[(size_t)(c0 + r) * Aa + kb + kq * 4];
        *(float2*)&Xs[r][kq * 4]     = make_float2(xv4.x, xv4.y);
        *(float2*)&Xs[r][kq * 4 + 2] = make_float2(xv4.z, xv4.w);
        *(float2*)&Ws[r][kq * 4]     = make_float2(wv4.x, wv4.y);
        *(float2*)&Ws[r][kq * 4 + 2] = make_float2(wv4.z, wv4.w);
    }
    __syncthreads();

    // Inputs consumed; let the dependent kernel's prologue start now.
    cudaTriggerProgrammaticLaunchCompletion();

    const int tx = tid & 15;          // col sub-index (stride 16)
    const int ty = tid >> 4;          // row 0..31 (handles rows ty, ty+32)
    unsigned long long acc[8];
#pragma unroll
    for (int i = 0; i < 8; ++i) acc[i] = 0ull;

#pragma unroll 4
    for (int kk = 0; kk < 64; kk += 2) {
        unsigned long long xv0, xv1, wv[4];
        xv0 = *(const unsigned long long*)&Xs[ty][kk];
        xv1 = *(const unsigned long long*)&Xs[ty + 32][kk];
#pragma unroll
        for (int u = 0; u < 4; ++u)
            wv[u] = *(const unsigned long long*)&Ws[tx + 16 * u][kk];
#pragma unroll
        for (int u = 0; u < 4; ++u) {
            asm("fma.rn.f32x2 %0, %1, %2, %0;" : "+l"(acc[u])     : "l"(xv0), "l"(wv[u]));
            asm("fma.rn.f32x2 %0, %1, %2, %0;" : "+l"(acc[4 + u]) : "l"(xv1), "l"(wv[u]));
        }
    }

    float* base = g_part + (size_t)kt * (2 * Nn * Cc);
#pragma unroll
    for (int i = 0; i < 2; ++i)
#pragma unroll
        for (int u = 0; u < 4; ++u) {
            const unsigned long long a = acc[i * 4 + u];
            const float lo = __uint_as_float((unsigned int)(a & 0xffffffffull));
            const float hi = __uint_as_float((unsigned int)(a >> 32));
            base[(size_t)(m0 + ty + 32 * i) * Cc + c0 + tx + 16 * u] = lo + hi;
        }
}

// ===========================================================================
// K2: prologue (lists, bias) overlaps K1 via PDL; gridDependencySynchronize
// before consuming g_part; sigma + log-softmax + NLL; atomic mean tail.
// ===========================================================================
__device__ __forceinline__ float sum8(int row, int col) {
    float v = 0.f;
#pragma unroll
    for (int q = 0; q < KSPLIT; ++q)
        v += g_part[q * (2 * Nn * Cc) + row * Cc + col];
    return v;
}

__global__ __launch_bounds__(NT2, 1)
void isda_loss_kernel(const float* __restrict__ bias,
                      const int* __restrict__ ts,
                      const int* __restrict__ tt,
                      float* __restrict__ out)
{
    __shared__ int mlist[Nn], tlist[Nn];
    __shared__ float pk[Nn];
    __shared__ float red[8];
    __shared__ float sh_yk;
    __shared__ int wM[4], wT[4];

    const int tid  = threadIdx.x;
    const int n    = blockIdx.x;
    const int lane = tid & 31;
    const int warp = tid >> 5;

    // ---------------- Prologue: independent of K1's output ----------------
    int my_ts = 0, my_tt = 0;
    if (tid < Nn) { my_ts = ts[tid]; my_tt = tt[tid]; }
    const int k = tt[n];
    const float my_bias = bias[tid];

    {
        const bool valid = tid < Nn;
        const bool pM = valid && (my_ts == k);
        const bool pT = valid && (my_tt == k);
        const unsigned mM = __ballot_sync(0xffffffffu, pM);
        const unsigned mT = __ballot_sync(0xffffffffu, pT);
        if (lane == 0 && warp < 4) { wM[warp] = __popc(mM); wT[warp] = __popc(mT); }
        __syncthreads();
        const unsigned lt = (1u << lane) - 1u;
        if (warp < 4) {
            int bM = 0, bT = 0;
#pragma unroll
            for (int w = 0; w < 4; ++w)
                if (w < warp) { bM += wM[w]; bT += wT[w]; }
            if (pM) mlist[bM + __popc(mM & lt)] = tid;
            if (pT) tlist[bT + __popc(mT & lt)] = tid;
        }
    }
    const int cnt = wM[0] + wM[1] + wM[2] + wM[3];
    const int tnt = wT[0] + wT[1] + wT[2] + wT[3];
    __syncthreads();

    // ---------------- Wait for K1's g_part to be complete ------------------
    cudaGridDependencySynchronize();

    if (tid < cnt) pk[tid] = sum8(mlist[tid], k);
    __syncthreads();

    const float invS = (cnt > 0) ? 1.0f / (float)cnt : 0.0f;  // w_cv zeroing
    const float invT = 1.0f / (float)tnt;                     // tnt >= 1 (n itself)
    const int c = tid;

    // Single pass: sums for mean + expanded-square sigma moments
    float sumpk = 0.f;
    for (int j = 0; j < cnt; ++j) sumpk += pk[j];
    float sumG = 0.f, s1 = 0.f, s2 = 0.f;
#pragma unroll 2
    for (int j = 0; j < cnt; ++j) {
        const float gv = sum8(mlist[j], c);
        const float a = gv - pk[j];
        sumG += gv; s1 += a; s2 += a * a;
    }
    float sumH = 0.f;
#pragma unroll 2
    for (int j = 0; j < tnt; ++j)
        sumH += sum8(Nn + tlist[j], c);

    const float dbar  = invS * (sumG - sumpk);   // Gbar[c] - Gbar[k]
    const float sigma = invS * (s2 - 2.0f * dbar * s1 + (float)cnt * dbar * dbar);
    float y = 0.5f * (sumG * invS + sumH * invT) + my_bias + 0.25f * sigma;

    // block max
    float mmax = y;
#pragma unroll
    for (int o = 16; o; o >>= 1) mmax = fmaxf(mmax, __shfl_xor_sync(0xffffffffu, mmax, o));
    if (lane == 0) red[warp] = mmax;
    __syncthreads();
    mmax = red[0];
#pragma unroll
    for (int w = 1; w < 8; ++w) mmax = fmaxf(mmax, red[w]);
    __syncthreads();

    float e = __expf(y - mmax);
#pragma unroll
    for (int o = 16; o; o >>= 1) e += __shfl_xor_sync(0xffffffffu, e, o);
    if (lane == 0) red[warp] = e;
    if (tid == k) sh_yk = y;
    __syncthreads();
    if (tid == 0) {
        float tot = 0.f;
#pragma unroll
        for (int w = 0; w < 8; ++w) tot += red[w];
        const float loss_n = -(sh_yk - mmax - __logf(tot));
        atomicAdd(out, loss_n * (1.0f / (float)Nn));
    }
}

// ---------------------------------------------------------------------------
extern "C" void kernel_launch(void* const* d_in, const int* in_sizes, int n_in,
                              void* d_out, int out_size) {
    const float* fc_weight = (const float*)d_in[0];   // (2C, A)
    const float* fc_bias   = (const float*)d_in[1];   // (2C,)
    const float* s_feat    = (const float*)d_in[2];   // (N, A)
    const float* t_feat    = (const float*)d_in[3];   // (N, A)
    const int*   target_s  = (const int*)d_in[4];     // (N,)
    const int*   target_t  = (const int*)d_in[5];     // (N,)
    float* out = (float*)d_out;

    isda_gemm_kernel<<<NB, NT1>>>(fc_weight, s_feat, t_feat, out);

    cudaLaunchAttribute attr[1];
    attr[0].id = cudaLaunchAttributeProgrammaticStreamSerialization;
    attr[0].val.programmaticStreamSerializationAllowed = 1;

    cudaLaunchConfig_t cfg2 = {};
    cfg2.gridDim  = dim3(NB, 1, 1);
    cfg2.blockDim = dim3(NT2, 1, 1);
    cfg2.attrs = attr;
    cfg2.numAttrs = 1;
    cudaLaunchKernelEx(&cfg2, isda_loss_kernel, fc_bias, target_s, target_t,
                       (float*)d_out);
}

// round 16
// speedup vs baseline: 1.0239x; 1.0239x over previous
#include <cuda_runtime.h>
#include <math.h>

#define Nn 128
#define Cc 256
#define Aa 512
#define NB 128
#define NT 256
#define KSPLIT 8
#define TS 66              // smem row stride (floats): even (8B-aligned rows)

// Scratch (device globals — no allocations allowed).
__device__ float g_part[KSPLIT * 2 * Nn * Cc]; // K-split partials of [G;H]

// ===========================================================================
// K1: [G;H] = [s;t] @ W[:C]^T  — 16 output tiles (64x64) x 8-way K-split.
// PDL-pipelined: ramp/stage/FMA read only const inputs and overlap the
// PREVIOUS replay's K2; all writes (g_part, out[0]=0) are deferred until
// after gridDependencySynchronize so no hazard with K2-prev's reads/atomics.
// ===========================================================================
__global__ __launch_bounds__(NT, 1)
void isda_gemm_kernel(const float* __restrict__ W,
                      const float* __restrict__ s,
                      const float* __restrict__ t,
                      float* __restrict__ out)
{
    __shared__ float Xs[64][TS];
    __shared__ float Ws[64][TS];
    const int tid = threadIdx.x;
    const int bid = blockIdx.x;

    const int mt = bid & 3;
    const int ct = (bid >> 2) & 3;
    const int kt = bid >> 4;
    const int m0 = mt * 64, c0 = ct * 64, kb = kt * 64;

    const float* xbase = (mt < 2) ? (s + (size_t)m0 * Aa)
                                  : (t + (size_t)(m0 - 128) * Aa);
#pragma unroll
    for (int i = 0; i < 4; ++i) {
        const int idx = tid + i * 256;            // 0..1023
        const int r = idx >> 4, kq = idx & 15;
        const float4 xv4 = *(const float4*)&xbase[(size_t)r * Aa + kb + kq * 4];
        const float4 wv4 = *(const float4*)&W[(size_t)(c0 + r) * Aa + kb + kq * 4];
        *(float2*)&Xs[r][kq * 4]     = make_float2(xv4.x, xv4.y);
        *(float2*)&Xs[r][kq * 4 + 2] = make_float2(xv4.z, xv4.w);
        *(float2*)&Ws[r][kq * 4]     = make_float2(wv4.x, wv4.y);
        *(float2*)&Ws[r][kq * 4 + 2] = make_float2(wv4.z, wv4.w);
    }
    __syncthreads();

    // Inputs consumed; allow the dependent kernel (K2) to start its ramp.
    cudaTriggerProgrammaticLaunchCompletion();

    const int tx = tid & 15;          // col sub-index (stride 16)
    const int ty = tid >> 4;          // row sub-index (stride 16)
    unsigned long long acc[16];
#pragma unroll
    for (int i = 0; i < 16; ++i) acc[i] = 0ull;

#pragma unroll 4
    for (int kk = 0; kk < 64; kk += 2) {
        unsigned long long xv[4], wv[4];
#pragma unroll
        for (int i = 0; i < 4; ++i)
            xv[i] = *(const unsigned long long*)&Xs[ty + 16 * i][kk];
#pragma unroll
        for (int u = 0; u < 4; ++u)
            wv[u] = *(const unsigned long long*)&Ws[tx + 16 * u][kk];
#pragma unroll
        for (int i = 0; i < 4; ++i)
#pragma unroll
            for (int u = 0; u < 4; ++u)
                asm("fma.rn.f32x2 %0, %1, %2, %0;"
                    : "+l"(acc[i * 4 + u]) : "l"(xv[i]), "l"(wv[u]));
    }

    // ---- Hazard point: wait for the previous replay's K2 before writing ----
    cudaGridDependencySynchronize();

    if (bid == 0 && tid == 0) out[0] = 0.0f;

    float* base = g_part + (size_t)kt * (2 * Nn * Cc);
#pragma unroll
    for (int i = 0; i < 4; ++i)
#pragma unroll
        for (int u = 0; u < 4; ++u) {
            const unsigned long long a = acc[i * 4 + u];
            const float lo = __uint_as_float((unsigned int)(a & 0xffffffffull));
            const float hi = __uint_as_float((unsigned int)(a >> 32));
            base[(size_t)(m0 + ty + 16 * i) * Cc + c0 + tx + 16 * u] = lo + hi;
        }
}

// ===========================================================================
// K2: triggers at entry (launch-gating only — the NEXT replay's K1 defers
// its writes behind its own gridsync). Prologue overlaps K1 via PDL;
// gridsync before consuming g_part; sigma + log-softmax + NLL; atomic tail.
// ===========================================================================
__device__ __forceinline__ float sum8(int row, int col) {
    float v = 0.f;
#pragma unroll
    for (int q = 0; q < KSPLIT; ++q)
        v += g_part[q * (2 * Nn * Cc) + row * Cc + col];
    return v;
}

__global__ __launch_bounds__(NT, 1)
void isda_loss_kernel(const float* __restrict__ bias,
                      const int* __restrict__ ts,
                      const int* __restrict__ tt,
                      float* __restrict__ out)
{
    __shared__ int mlist[Nn], tlist[Nn];
    __shared__ float pk[Nn];
    __shared__ float red[8];
    __shared__ float sh_yk;
    __shared__ int wM[4], wT[4];

    const int tid  = threadIdx.x;
    const int n    = blockIdx.x;
    const int lane = tid & 31;
    const int warp = tid >> 5;

    // Un-gate the next kernel's launch immediately (hazards handled by ITS sync).
    cudaTriggerProgrammaticLaunchCompletion();

    // ---------------- Prologue: independent of K1's output ----------------
    int my_ts = 0, my_tt = 0;
    if (tid < Nn) { my_ts = ts[tid]; my_tt = tt[tid]; }
    const int k = tt[n];
    const float my_bias = bias[tid];

    {
        const bool valid = tid < Nn;
        const bool pM = valid && (my_ts == k);
        const bool pT = valid && (my_tt == k);
        const unsigned mM = __ballot_sync(0xffffffffu, pM);
        const unsigned mT = __ballot_sync(0xffffffffu, pT);
        if (lane == 0 && warp < 4) { wM[warp] = __popc(mM); wT[warp] = __popc(mT); }
        __syncthreads();
        const unsigned lt = (1u << lane) - 1u;
        if (warp < 4) {
            int bM = 0, bT = 0;
#pragma unroll
            for (int w = 0; w < 4; ++w)
                if (w < warp) { bM += wM[w]; bT += wT[w]; }
            if (pM) mlist[bM + __popc(mM & lt)] = tid;
            if (pT) tlist[bT + __popc(mT & lt)] = tid;
        }
    }
    const int cnt = wM[0] + wM[1] + wM[2] + wM[3];
    const int tnt = wT[0] + wT[1] + wT[2] + wT[3];
    __syncthreads();

    // ---------------- Wait for K1's g_part to be complete ------------------
    cudaGridDependencySynchronize();

    if (tid < cnt) pk[tid] = sum8(mlist[tid], k);
    __syncthreads();

    const float invS = (cnt > 0) ? 1.0f / (float)cnt : 0.0f;  // w_cv zeroing
    const float invT = 1.0f / (float)tnt;                     // tnt >= 1 (n itself)
    const int c = tid;

    // Single pass: sums for mean + expanded-square sigma moments
    float sumpk = 0.f;
    for (int j = 0; j < cnt; ++j) sumpk += pk[j];
    float sumG = 0.f, s1 = 0.f, s2 = 0.f;
#pragma unroll 2
    for (int j = 0; j < cnt; ++j) {
        const float gv = sum8(mlist[j], c);
        const float a = gv - pk[j];
        sumG += gv; s1 += a; s2 += a * a;
    }
    float sumH = 0.f;
#pragma unroll 2
    for (int j = 0; j < tnt; ++j)
        sumH += sum8(Nn + tlist[j], c);

    const float dbar  = invS * (sumG - sumpk);   // Gbar[c] - Gbar[k]
    const float sigma = invS * (s2 - 2.0f * dbar * s1 + (float)cnt * dbar * dbar);
    float y = 0.5f * (sumG * invS + sumH * invT) + my_bias + 0.25f * sigma;

    // block max
    float mmax = y;
#pragma unroll
    for (int o = 16; o; o >>= 1) mmax = fmaxf(mmax, __shfl_xor_sync(0xffffffffu, mmax, o));
    if (lane == 0) red[warp] = mmax;
    __syncthreads();
    mmax = red[0];
#pragma unroll
    for (int w = 1; w < 8; ++w) mmax = fmaxf(mmax, red[w]);
    __syncthreads();

    float e = __expf(y - mmax);
#pragma unroll
    for (int o = 16; o; o >>= 1) e += __shfl_xor_sync(0xffffffffu, e, o);
    if (lane == 0) red[warp] = e;
    if (tid == k) sh_yk = y;
    __syncthreads();
    if (tid == 0) {
        float tot = 0.f;
#pragma unroll
        for (int w = 0; w < 8; ++w) tot += red[w];
        const float loss_n = -(sh_yk - mmax - __logf(tot));
        atomicAdd(out, loss_n * (1.0f / (float)Nn));
    }
}

// ---------------------------------------------------------------------------
extern "C" void kernel_launch(void* const* d_in, const int* in_sizes, int n_in,
                              void* d_out, int out_size) {
    const float* fc_weight = (const float*)d_in[0];   // (2C, A)
    const float* fc_bias   = (const float*)d_in[1];   // (2C,)
    const float* s_feat    = (const float*)d_in[2];   // (N, A)
    const float* t_feat    = (const float*)d_in[3];   // (N, A)
    const int*   target_s  = (const int*)d_in[4];     // (N,)
    const int*   target_t  = (const int*)d_in[5];     // (N,)
    float* out = (float*)d_out;

    cudaLaunchAttribute attr[1];
    attr[0].id = cudaLaunchAttributeProgrammaticStreamSerialization;
    attr[0].val.programmaticStreamSerializationAllowed = 1;

    cudaLaunchConfig_t cfg1 = {};
    cfg1.gridDim  = dim3(NB, 1, 1);
    cfg1.blockDim = dim3(NT, 1, 1);
    cfg1.attrs = attr;
    cfg1.numAttrs = 1;
    cudaLaunchKernelEx(&cfg1, isda_gemm_kernel, fc_weight, s_feat, t_feat,
                       (float*)d_out);

    cudaLaunchConfig_t cfg2 = {};
    cfg2.gridDim  = dim3(NB, 1, 1);
    cfg2.blockDim = dim3(NT, 1, 1);
    cfg2.attrs = attr;
    cfg2.numAttrs = 1;
    cudaLaunchKernelEx(&cfg2, isda_loss_kernel, fc_bias, target_s, target_t,
                       (float*)d_out);
}